// round 6
// baseline (speedup 1.0000x reference)
#include <cuda_runtime.h>
#include <cuda_fp16.h>
#include <math.h>

#define PB  128
#define PH  100
#define PC  32
#define PK  4
#define PD  400
#define PDP 448          // padded K for MMA
#define PE  200
#define PCW 100
#define PN  (PB*PC)

#define KC   64          // k per chunk
#define NCH  7
#define AS   72          // smem row stride (halves)
#define A_PLANE (128*AS)     // 9216 halves (rows 100..127 unwritten, harmless)
#define B_PLANE (208*AS)     // 14976 halves (rows 200..207 unwritten, harmless)
#define BUF_HALVES (2*A_PLANE + 2*B_PLANE)   // 48384
#define SMEMA_BYTES (2*BUF_HALVES*2)         // 193536 B

typedef unsigned long long ull;
typedef unsigned int uint;

__device__ __align__(16) float u_g[PB*PK*PD];
__device__ __align__(16) float uW_g[PB*PK*PE];
__device__ __align__(16) float sk_g[PN*PK];
__device__ unsigned work_ctr;

// preconverted f16 hi/lo planes
__device__ __align__(16) __half hisH[PB*PK*PH*PDP];   // [bk][h][448]
__device__ __align__(16) __half hisL[PB*PK*PH*PDP];
__device__ __align__(16) __half WTh[PK*PE*PDP];       // [k][e][448] (transposed)
__device__ __align__(16) __half WTl[PK*PE*PDP];

// ---- helpers ----
__device__ __forceinline__ ull pack2(float a, float b) {
    ull r; asm("mov.b64 %0, {%1, %2};" : "=l"(r) : "f"(a), "f"(b)); return r;
}
__device__ __forceinline__ void unpack2(ull v, float& a, float& b) {
    asm("mov.b64 {%0, %1}, %2;" : "=f"(a), "=f"(b) : "l"(v));
}
__device__ __forceinline__ void fma2(ull& d, ull a, ull b) {
    asm("fma.rn.f32x2 %0, %1, %2, %0;" : "+l"(d) : "l"(a), "l"(b));
}
__device__ __forceinline__ float tanh_fast(float x) {
    return __fdividef(2.f, 1.f + __expf(-2.f * x)) - 1.f;
}
__device__ __forceinline__ void mma16816(
    float& c0, float& c1, float& c2, float& c3,
    uint a0, uint a1, uint a2, uint a3, uint b0, uint b1)
{
    asm volatile(
        "mma.sync.aligned.m16n8k16.row.col.f32.f16.f16.f32 "
        "{%0,%1,%2,%3}, {%4,%5,%6,%7}, {%8,%9}, {%0,%1,%2,%3};"
        : "+f"(c0), "+f"(c1), "+f"(c2), "+f"(c3)
        : "r"(a0), "r"(a1), "r"(a2), "r"(a3), "r"(b0), "r"(b1));
}
__device__ __forceinline__ ull pack4h(float x0, float x1, float x2, float x3) {
    __half2 h01 = __halves2half2(__float2half_rn(x0), __float2half_rn(x1));
    __half2 h23 = __halves2half2(__float2half_rn(x2), __float2half_rn(x3));
    uint u0 = *(uint*)&h01, u1 = *(uint*)&h23;
    return (ull)u0 | ((ull)u1 << 32);
}
__device__ __forceinline__ unsigned smem_u32(const void* p) {
    return (unsigned)__cvta_generic_to_shared(p);
}
__device__ __forceinline__ void cp16(__half* dst, const __half* src) {
    asm volatile("cp.async.cg.shared.global [%0], [%1], 16;"
                 :: "r"(smem_u32(dst)), "l"(src));
}
__device__ __forceinline__ void cp_commit() {
    asm volatile("cp.async.commit_group;");
}
template <int N>
__device__ __forceinline__ void cp_wait() {
    asm volatile("cp.async.wait_group %0;" :: "n"(N));
}

__global__ void resetK() { work_ctr = 0; }

// ---- P1: his -> hisH/hisL (padded, k-major) ----
__global__ void __launch_bounds__(256) preconvHis(const float* __restrict__ his) {
    const int u = blockIdx.x*256 + threadIdx.x;   // 512*100*112 units
    if (u >= PB*PK*PH*112) return;
    const int bkh = u / 112, c4 = u - bkh*112;
    const int bk = bkh / PH, h = bkh - bk*PH;
    const int b = bk >> 2, k = bk & 3;
    const size_t dst = (size_t)(bk*PH + h)*PDP + c4*4;
    if (c4 < 100) {
        float4 v = *(const float4*)(his + ((size_t)b*PH + h)*(PK*PD) + k*PD + c4*4);
        float h0 = __half2float(__float2half_rn(v.x));
        float h1 = __half2float(__float2half_rn(v.y));
        float h2 = __half2float(__float2half_rn(v.z));
        float h3 = __half2float(__float2half_rn(v.w));
        *(ull*)(hisH + dst) = pack4h(v.x, v.y, v.z, v.w);
        *(ull*)(hisL + dst) = pack4h(v.x - h0, v.y - h1, v.z - h2, v.w - h3);
    } else {
        *(ull*)(hisH + dst) = 0ull;
        *(ull*)(hisL + dst) = 0ull;
    }
}

// ---- P2: W_att -> WTh/WTl transposed [k][e][448] ----
__global__ void __launch_bounds__(256) preconvW(const float* __restrict__ W_att) {
    const int u = blockIdx.x*256 + threadIdx.x;   // 4*200*112 units
    if (u >= PK*PE*112) return;
    const int ke = u / 112, d4 = u - ke*112;
    const int k = ke / PE, e = ke - k*PE;
    const size_t dst = (size_t)ke*PDP + d4*4;
    if (d4 < 100) {
        float w0 = W_att[((size_t)k*PD + d4*4    )*PE + e];
        float w1 = W_att[((size_t)k*PD + d4*4 + 1)*PE + e];
        float w2 = W_att[((size_t)k*PD + d4*4 + 2)*PE + e];
        float w3 = W_att[((size_t)k*PD + d4*4 + 3)*PE + e];
        float h0 = __half2float(__float2half_rn(w0));
        float h1 = __half2float(__float2half_rn(w1));
        float h2 = __half2float(__float2half_rn(w2));
        float h3 = __half2float(__float2half_rn(w3));
        *(ull*)(WTh + dst) = pack4h(w0, w1, w2, w3);
        *(ull*)(WTl + dst) = pack4h(w0-h0, w1-h1, w2-h2, w3-h3);
    } else {
        *(ull*)(WTh + dst) = 0ull;
        *(ull*)(WTl + dst) = 0ull;
    }
}

// -----------------------------------------------------------------------------
// Kernel A: persistent, work-steal over 512 (b,k). Split-f16 MMA, tiles via
// cp.async from preconverted planes, double-buffered over 7 k-chunks.
// -----------------------------------------------------------------------------
__global__ void __launch_bounds__(512, 1) kernelA(
    const float* __restrict__ his,
    const float* __restrict__ b_att, const float* __restrict__ q_att,
    const float* __restrict__ W_lin, const float* __restrict__ b_lin)
{
    extern __shared__ __half smh[];

    __shared__ float s_s[PH];
    __shared__ float u_s[PD];
    __shared__ float qa_s[PE], ba_s[PE];
    __shared__ float red_s[2];
    __shared__ int item_s;

    const int tid  = threadIdx.x;
    const int warp = tid >> 5;
    const int lane = tid & 31;
    const int g    = lane >> 2;
    const int qq   = lane & 3;
    const int mrow0 = (warp >> 1) * 16;
    const int nbase = (warp & 1) * 104;

    while (true) {
        if (tid == 0) item_s = (int)atomicAdd(&work_ctr, 1u);
        __syncthreads();
        const int bk = item_s;
        if (bk >= PB*PK) return;
        const int b = bk >> 2;
        const int k = bk & 3;

        const float* hisB = his + ((size_t)b*PH)*(PK*PD) + (size_t)k*PD;
        const __half* srcA_H = hisH + (size_t)bk*PH*PDP;
        const __half* srcA_L = hisL + (size_t)bk*PH*PDP;
        const __half* srcB_H = WTh + (size_t)k*PE*PDP;
        const __half* srcB_L = WTl + (size_t)k*PE*PDP;

        for (int i = tid; i < PH; i += 512) s_s[i] = 0.f;
        for (int i = tid; i < PE; i += 512) {
            qa_s[i] = q_att[k*PE + i];
            ba_s[i] = b_att[k*PE + i];
        }

        // tile loader: A 100 rows x 8 chunks x 2 planes = 1600 units,
        //              B 200 rows x 8 chunks x 2 planes = 3200 units
        auto load_tile = [&](int buf, int k0) {
            __half* aHi = smh + buf*BUF_HALVES;
            __half* aLo = aHi + A_PLANE;
            __half* bHi = aLo + A_PLANE;
            __half* bLo = bHi + B_PLANE;
            #pragma unroll
            for (int it = 0; it < 4; ++it) {
                int u = tid + it*512;
                if (u < 1600) {
                    int row = u >> 4, rem = u & 15;
                    int pl = rem >> 3, c = rem & 7;
                    __half* d = (pl ? aLo : aHi) + row*AS + c*8;
                    const __half* s = (pl ? srcA_L : srcA_H) + (size_t)row*PDP + k0 + c*8;
                    cp16(d, s);
                }
            }
            #pragma unroll
            for (int it = 0; it < 7; ++it) {
                int u = tid + it*512;
                if (u < 3200) {
                    int row = u >> 4, rem = u & 15;
                    int pl = rem >> 3, c = rem & 7;
                    __half* d = (pl ? bLo : bHi) + row*AS + c*8;
                    const __half* s = (pl ? srcB_L : srcB_H) + (size_t)row*PDP + k0 + c*8;
                    cp16(d, s);
                }
            }
        };

        float c[13][4];
        #pragma unroll
        for (int t = 0; t < 13; ++t)
            #pragma unroll
            for (int j = 0; j < 4; ++j) c[t][j] = 0.f;

        load_tile(0, 0);
        cp_commit();

        for (int ch = 0; ch < NCH; ++ch) {
            const int buf = ch & 1;
            if (ch < NCH - 1) {
                load_tile(buf ^ 1, (ch+1)*KC);
                cp_commit();
                cp_wait<1>();
            } else {
                cp_wait<0>();
            }
            __syncthreads();

            const __half* aHi = smh + buf*BUF_HALVES;
            const __half* aLo = aHi + A_PLANE;
            const __half* bHi = aLo + A_PLANE;
            const __half* bLo = bHi + B_PLANE;

            #pragma unroll
            for (int ks = 0; ks < 4; ++ks) {
                const int kk = ks * 16;
                const int abase = (mrow0 + g)*AS + kk + qq*2;
                uint ah0 = *(const uint*)(aHi + abase);
                uint ah1 = *(const uint*)(aHi + abase + 8*AS);
                uint ah2 = *(const uint*)(aHi + abase + 8);
                uint ah3 = *(const uint*)(aHi + abase + 8*AS + 8);
                uint al0 = *(const uint*)(aLo + abase);
                uint al1 = *(const uint*)(aLo + abase + 8*AS);
                uint al2 = *(const uint*)(aLo + abase + 8);
                uint al3 = *(const uint*)(aLo + abase + 8*AS + 8);
                #pragma unroll
                for (int t = 0; t < 13; ++t) {
                    const int boff = (nbase + t*8 + g)*AS + kk + qq*2;
                    uint bh0 = *(const uint*)(bHi + boff);
                    uint bh1 = *(const uint*)(bHi + boff + 8);
                    uint bl0 = *(const uint*)(bLo + boff);
                    uint bl1 = *(const uint*)(bLo + boff + 8);
                    mma16816(c[t][0], c[t][1], c[t][2], c[t][3],
                             ah0, ah1, ah2, ah3, bh0, bh1);
                    mma16816(c[t][0], c[t][1], c[t][2], c[t][3],
                             ah0, ah1, ah2, ah3, bl0, bl1);
                    mma16816(c[t][0], c[t][1], c[t][2], c[t][3],
                             al0, al1, al2, al3, bh0, bh1);
                }
            }
            __syncthreads();
        }

        // epilogue: s[h] += sum_e q*tanh(z + b_att)
        {
            const int r0 = mrow0 + g, r1 = r0 + 8;
            float p0 = 0.f, p1 = 0.f;
            #pragma unroll
            for (int t = 0; t < 13; ++t) {
                const int e0 = nbase + t*8 + qq*2;
                if (e0 < PE) {
                    const float q0 = qa_s[e0],   bb0 = ba_s[e0];
                    const float q1 = qa_s[e0+1], bb1 = ba_s[e0+1];
                    p0 += q0 * tanh_fast(c[t][0] + bb0);
                    p0 += q1 * tanh_fast(c[t][1] + bb1);
                    p1 += q0 * tanh_fast(c[t][2] + bb0);
                    p1 += q1 * tanh_fast(c[t][3] + bb1);
                }
            }
            if (r0 < PH) atomicAdd(&s_s[r0], p0);
            if (r1 < PH) atomicAdd(&s_s[r1], p1);
        }
        __syncthreads();

        // softmax over h
        if (tid < 32) {
            float m = -1e30f;
            for (int h = tid; h < PH; h += 32) m = fmaxf(m, s_s[h]);
            #pragma unroll
            for (int off = 16; off; off >>= 1)
                m = fmaxf(m, __shfl_xor_sync(0xffffffffu, m, off));
            if (tid == 0) { red_s[0] = m; red_s[1] = 0.f; }
        }
        __syncthreads();
        const float mx = red_s[0];
        if (tid < PH) {
            float ex = __expf(s_s[tid] - mx);
            s_s[tid] = ex;
            atomicAdd(&red_s[1], ex);
        }
        __syncthreads();
        const float inv = 1.f / red_s[1];

        for (int d = tid; d < PD; d += 512) {
            float a0 = 0.f, a1 = 0.f;
            #pragma unroll 4
            for (int h = 0; h < PH; h += 2) {
                a0 += s_s[h]   * hisB[(size_t)h*(PK*PD) + d];
                a1 += s_s[h+1] * hisB[(size_t)(h+1)*(PK*PD) + d];
            }
            float uu = (a0 + a1) * inv;
            u_s[d] = uu;
            u_g[bk*PD + d] = uu;
        }
        __syncthreads();

        for (int e = tid; e < PE; e += 512) {
            float a0 = b_lin[e], a1 = 0.f, a2 = 0.f, a3 = 0.f;
            #pragma unroll 2
            for (int d = 0; d < PD; d += 4) {
                a0 += u_s[d]   * W_lin[(d)*PE + e];
                a1 += u_s[d+1] * W_lin[(d+1)*PE + e];
                a2 += u_s[d+2] * W_lin[(d+2)*PE + e];
                a3 += u_s[d+3] * W_lin[(d+3)*PE + e];
            }
            uW_g[bk*PE + e] = (a0 + a1) + (a2 + a3);
        }
        __syncthreads();
    }
}

// ---- Kernel C ----
__global__ void __launch_bounds__(256) kernelC(
    const float* __restrict__ cwt, const float* __restrict__ W_lin,
    const float* __restrict__ q_vec)
{
    extern __shared__ float sm[];
    float* W2 = sm;
    float* cw = W2 + PCW*PE;

    const int tid = threadIdx.x;
    const int tx = tid & 7;
    const int ty = tid >> 3;
    const int row0 = blockIdx.x * 64;

    for (int i = tid; i < PCW*PE; i += 256) W2[i] = W_lin[PD*PE + i];
    for (int i = tid; i < 64*PCW; i += 256) cw[i] = cwt[(size_t)row0*PCW + i];
    __syncthreads();

    ull acc2[2][12];
    float accS[2] = {0.f, 0.f};
    #pragma unroll
    for (int r = 0; r < 2; ++r)
        #pragma unroll
        for (int j = 0; j < 12; ++j) acc2[r][j] = 0ull;

    const float* c0p = cw + (ty*2)*PCW;
    const float* c1p = c0p + PCW;

    #pragma unroll 2
    for (int f = 0; f < PCW; ++f) {
        const float c0 = c0p[f], c1 = c1p[f];
        const ull cc0 = pack2(c0, c0), cc1 = pack2(c1, c1);
        const float* wrow = W2 + f*PE + tx*2;
        #pragma unroll
        for (int j = 0; j < 12; ++j) {
            ull w2v = *(const ull*)(wrow + j*16);
            fma2(acc2[0][j], cc0, w2v);
            fma2(acc2[1][j], cc1, w2v);
        }
        const float wl = W2[f*PE + 192 + tx];
        accS[0] += c0 * wl;
        accS[1] += c1 * wl;
    }

    #pragma unroll
    for (int rr = 0; rr < 2; ++rr) {
        const int gidx = row0 + ty*2 + rr;
        const int n = gidx >> 2, kk = gidx & 3, b = n >> 5;
        const float* uWp = uW_g + ((b << 2) + kk)*PE;
        float p = 0.f;
        #pragma unroll
        for (int j = 0; j < 12; ++j) {
            const int e = j*16 + tx*2;
            float z0, z1; unpack2(acc2[rr][j], z0, z1);
            p += q_vec[e]     * tanh_fast(z0 + uWp[e]);
            p += q_vec[e + 1] * tanh_fast(z1 + uWp[e + 1]);
        }
        {
            const int e = 192 + tx;
            p += q_vec[e] * tanh_fast(accS[rr] + uWp[e]);
        }
        p += __shfl_xor_sync(0xffffffffu, p, 1);
        p += __shfl_xor_sync(0xffffffffu, p, 2);
        p += __shfl_xor_sync(0xffffffffu, p, 4);
        if (tx == 0) sk_g[gidx] = p;
    }
}

// ---- Kernel D ----
__global__ void __launch_bounds__(128) kernelD(
    const float* __restrict__ cdd,
    float* __restrict__ out_scores, float* __restrict__ out_u)
{
    const int n = blockIdx.x;
    const int b = n >> 5;
    const int tid = threadIdx.x;
    const int k = tid >> 5;
    const int lane = tid & 31;
    __shared__ float dot_s[4];

    const float* up = u_g + (size_t)((b << 2) + k)*PD;
    const float* cp = cdd + ((size_t)n*PK + k)*PD;
    float a = 0.f;
    for (int d = lane; d < PD; d += 32) a += up[d] * cp[d];
    #pragma unroll
    for (int off = 16; off; off >>= 1)
        a += __shfl_xor_sync(0xffffffffu, a, off);
    if (lane == 0) dot_s[k] = a;
    __syncthreads();

    if (tid == 0) {
        const float s0 = sk_g[n*4], s1 = sk_g[n*4+1], s2 = sk_g[n*4+2], s3 = sk_g[n*4+3];
        const float m = fmaxf(fmaxf(s0, s1), fmaxf(s2, s3));
        const float w0 = __expf(s0 - m), w1 = __expf(s1 - m);
        const float w2 = __expf(s2 - m), w3 = __expf(s3 - m);
        out_scores[n] = (w0*dot_s[0] + w1*dot_s[1] + w2*dot_s[2] + w3*dot_s[3])
                        / (w0 + w1 + w2 + w3);
    }

    const float4* u4 = (const float4*)(u_g + (size_t)b*PK*PD);
    float4* o4 = (float4*)(out_u + (size_t)n*PK*PD);
    #pragma unroll
    for (int i = tid; i < PK*PD/4; i += 128) o4[i] = u4[i];
}

extern "C" void kernel_launch(void* const* d_in, const int* in_sizes, int n_in,
                              void* d_out, int out_size)
{
    const float* his   = (const float*)d_in[0];
    const float* cdd   = (const float*)d_in[1];
    const float* cwt   = (const float*)d_in[2];
    const float* W_att = (const float*)d_in[3];
    const float* b_att = (const float*)d_in[4];
    const float* q_att = (const float*)d_in[5];
    const float* W_lin = (const float*)d_in[6];
    const float* b_lin = (const float*)d_in[7];
    const float* q_vec = (const float*)d_in[8];
    float* out = (float*)d_out;
    (void)in_sizes; (void)n_in; (void)out_size;

    resetK<<<1, 1>>>();
    preconvHis<<<(PB*PK*PH*112 + 255)/256, 256>>>(his);
    preconvW<<<(PK*PE*112 + 255)/256, 256>>>(W_att);

    cudaFuncSetAttribute(kernelA, cudaFuncAttributeMaxDynamicSharedMemorySize, SMEMA_BYTES);
    kernelA<<<148, 512, SMEMA_BYTES>>>(his, b_att, q_att, W_lin, b_lin);

    const int smemC = (PCW*PE + 64*PCW) * (int)sizeof(float);
    cudaFuncSetAttribute(kernelC, cudaFuncAttributeMaxDynamicSharedMemorySize, smemC);
    kernelC<<<(PN*PK)/64, 256, smemC>>>(cwt, W_lin, q_vec);

    kernelD<<<PN, 128>>>(cdd, out, out + PN);
}

// round 7
// speedup vs baseline: 1.3593x; 1.3593x over previous
#include <cuda_runtime.h>
#include <cuda_fp16.h>
#include <math.h>

#define PB  128
#define PH  100
#define PC  32
#define PK  4
#define PD  400
#define PDP 448
#define PE  200
#define PCW 100
#define PN  (PB*PC)

#define KC   64
#define NCH  7
#define AS   72                      // smem row stride (halves) = 144B
#define A_PLANE (64*AS)              // 4608 halves
#define B_PLANE (208*AS)             // 14976 halves
#define BUF_HALVES (2*A_PLANE + 2*B_PLANE)     // 39168 halves
#define SMEMA_BYTES (BUF_HALVES*2)             // 78336 B (single buffer)

typedef unsigned long long ull;
typedef unsigned int uint;

__device__ __align__(16) float u_g[PB*PK*PD];
__device__ __align__(16) float uW_g[PB*PK*PE];
__device__ __align__(16) float sk_g[PN*PK];
__device__ __align__(16) float s_g[PB*PK*PH];     // attention logits

__device__ __align__(16) __half hisH[PB*PK*PH*PDP];
__device__ __align__(16) __half hisL[PB*PK*PH*PDP];
__device__ __align__(16) __half WTh[PK*PE*PDP];
__device__ __align__(16) __half WTl[PK*PE*PDP];

// ---- helpers ----
__device__ __forceinline__ ull pack2(float a, float b) {
    ull r; asm("mov.b64 %0, {%1, %2};" : "=l"(r) : "f"(a), "f"(b)); return r;
}
__device__ __forceinline__ void unpack2(ull v, float& a, float& b) {
    asm("mov.b64 {%0, %1}, %2;" : "=f"(a), "=f"(b) : "l"(v));
}
__device__ __forceinline__ void fma2(ull& d, ull a, ull b) {
    asm("fma.rn.f32x2 %0, %1, %2, %0;" : "+l"(d) : "l"(a), "l"(b));
}
__device__ __forceinline__ float tanh_fast(float x) {
    return __fdividef(2.f, 1.f + __expf(-2.f * x)) - 1.f;
}
__device__ __forceinline__ void mma16816(
    float& c0, float& c1, float& c2, float& c3,
    uint a0, uint a1, uint a2, uint a3, uint b0, uint b1)
{
    asm volatile(
        "mma.sync.aligned.m16n8k16.row.col.f32.f16.f16.f32 "
        "{%0,%1,%2,%3}, {%4,%5,%6,%7}, {%8,%9}, {%0,%1,%2,%3};"
        : "+f"(c0), "+f"(c1), "+f"(c2), "+f"(c3)
        : "r"(a0), "r"(a1), "r"(a2), "r"(a3), "r"(b0), "r"(b1));
}
__device__ __forceinline__ ull pack4h(float x0, float x1, float x2, float x3) {
    __half2 h01 = __halves2half2(__float2half_rn(x0), __float2half_rn(x1));
    __half2 h23 = __halves2half2(__float2half_rn(x2), __float2half_rn(x3));
    uint u0 = *(uint*)&h01, u1 = *(uint*)&h23;
    return (ull)u0 | ((ull)u1 << 32);
}
__device__ __forceinline__ unsigned smem_u32(const void* p) {
    return (unsigned)__cvta_generic_to_shared(p);
}
__device__ __forceinline__ void cp16(__half* dst, const __half* src) {
    asm volatile("cp.async.cg.shared.global [%0], [%1], 16;"
                 :: "r"(smem_u32(dst)), "l"(src));
}
__device__ __forceinline__ void cp_commit() {
    asm volatile("cp.async.commit_group;");
}
template <int N>
__device__ __forceinline__ void cp_wait() {
    asm volatile("cp.async.wait_group %0;" :: "n"(N));
}

// ---- P1: his -> hisH/hisL padded k-major; also zero s_g ----
__global__ void __launch_bounds__(256) preconvHis(const float* __restrict__ his) {
    const int u = blockIdx.x*256 + threadIdx.x;
    if (u < PB*PK*PH) s_g[u] = 0.f;
    if (u >= PB*PK*PH*112) return;
    const int bkh = u / 112, c4 = u - bkh*112;
    const int bk = bkh / PH, h = bkh - bk*PH;
    const int b = bk >> 2, k = bk & 3;
    const size_t dst = (size_t)(bk*PH + h)*PDP + c4*4;
    if (c4 < 100) {
        float4 v = *(const float4*)(his + ((size_t)b*PH + h)*(PK*PD) + k*PD + c4*4);
        float h0 = __half2float(__float2half_rn(v.x));
        float h1 = __half2float(__float2half_rn(v.y));
        float h2 = __half2float(__float2half_rn(v.z));
        float h3 = __half2float(__float2half_rn(v.w));
        *(ull*)(hisH + dst) = pack4h(v.x, v.y, v.z, v.w);
        *(ull*)(hisL + dst) = pack4h(v.x - h0, v.y - h1, v.z - h2, v.w - h3);
    } else {
        *(ull*)(hisH + dst) = 0ull;
        *(ull*)(hisL + dst) = 0ull;
    }
}

// ---- P2: W_att -> WTh/WTl transposed [k][e][448] ----
__global__ void __launch_bounds__(256) preconvW(const float* __restrict__ W_att) {
    const int u = blockIdx.x*256 + threadIdx.x;
    if (u >= PK*PE*112) return;
    const int ke = u / 112, d4 = u - ke*112;
    const int k = ke / PE, e = ke - k*PE;
    const size_t dst = (size_t)ke*PDP + d4*4;
    if (d4 < 100) {
        float w0 = W_att[((size_t)k*PD + d4*4    )*PE + e];
        float w1 = W_att[((size_t)k*PD + d4*4 + 1)*PE + e];
        float w2 = W_att[((size_t)k*PD + d4*4 + 2)*PE + e];
        float w3 = W_att[((size_t)k*PD + d4*4 + 3)*PE + e];
        float h0 = __half2float(__float2half_rn(w0));
        float h1 = __half2float(__float2half_rn(w1));
        float h2 = __half2float(__float2half_rn(w2));
        float h3 = __half2float(__float2half_rn(w3));
        *(ull*)(WTh + dst) = pack4h(w0, w1, w2, w3);
        *(ull*)(WTl + dst) = pack4h(w0-h0, w1-h1, w2-h2, w3-h3);
    } else {
        *(ull*)(WTh + dst) = 0ull;
        *(ull*)(WTl + dst) = 0ull;
    }
}

// -----------------------------------------------------------------------------
// Kernel A1: flat GEMM. block = (mtile, k): 64 rows of M=12800 x full N=208.
// 8 warps = 4m x 2n; warp: m16 tile x 13 n8 tiles; split-f16 (3 MMA).
// Epilogue reduces q*tanh(z+b) over e into s_g[bk][h] via 2 atomics/row/warp.
// -----------------------------------------------------------------------------
__global__ void __launch_bounds__(256, 2) kernelA1(
    const float* __restrict__ b_att, const float* __restrict__ q_att)
{
    extern __shared__ __half smh[];
    __half* aHi = smh;
    __half* aLo = aHi + A_PLANE;
    __half* bHi = aLo + A_PLANE;
    __half* bLo = bHi + B_PLANE;

    const int tid  = threadIdx.x;
    const int warp = tid >> 5;
    const int lane = tid & 31;
    const int g    = lane >> 2;
    const int qq   = lane & 3;
    const int mrow0 = (warp >> 1) * 16;        // 0,16,32,48
    const int nbase = (warp & 1) * 104;

    const int mtile = blockIdx.x;              // 0..199
    const int k     = blockIdx.y;              // 0..3
    const int r0g   = mtile * 64;              // global row base

    const __half* srcBH = WTh + (size_t)k*PE*PDP;
    const __half* srcBL = WTl + (size_t)k*PE*PDP;

    float c[13][4];
    #pragma unroll
    for (int t = 0; t < 13; ++t)
        #pragma unroll
        for (int j = 0; j < 4; ++j) c[t][j] = 0.f;

    for (int ch = 0; ch < NCH; ++ch) {
        const int k0 = ch * KC;
        __syncthreads();   // prior compute done before overwrite

        // A: 64 rows x 8 chunks x 2 planes = 1024 units (4/thread)
        #pragma unroll
        for (int it = 0; it < 4; ++it) {
            int ua = tid + it*256;
            int row = ua >> 4, rem = ua & 15;
            int pl = rem >> 3, cc = rem & 7;
            int r = r0g + row;
            int b = r / 100, h = r - b*100;
            const __half* s = (pl ? hisL : hisH)
                + ((size_t)(b*4 + k)*PH + h)*PDP + k0 + cc*8;
            cp16((pl ? aLo : aHi) + row*AS + cc*8, s);
        }
        // B: 208 rows x 8 x 2 = 3328 units (13/thread), guard e<200
        #pragma unroll
        for (int it = 0; it < 13; ++it) {
            int ub = tid + it*256;
            int row = ub >> 4, rem = ub & 15;
            int pl = rem >> 3, cc = rem & 7;
            if (row < PE) {
                const __half* s = (pl ? srcBL : srcBH) + (size_t)row*PDP + k0 + cc*8;
                cp16((pl ? bLo : bHi) + row*AS + cc*8, s);
            }
        }
        cp_commit();
        cp_wait<0>();
        __syncthreads();

        #pragma unroll
        for (int ks = 0; ks < 4; ++ks) {
            const int kk = ks * 16;
            const int abase = (mrow0 + g)*AS + kk + qq*2;
            uint ah0 = *(const uint*)(aHi + abase);
            uint ah1 = *(const uint*)(aHi + abase + 8*AS);
            uint ah2 = *(const uint*)(aHi + abase + 8);
            uint ah3 = *(const uint*)(aHi + abase + 8*AS + 8);
            uint al0 = *(const uint*)(aLo + abase);
            uint al1 = *(const uint*)(aLo + abase + 8*AS);
            uint al2 = *(const uint*)(aLo + abase + 8);
            uint al3 = *(const uint*)(aLo + abase + 8*AS + 8);
            #pragma unroll
            for (int t = 0; t < 13; ++t) {
                const int boff = (nbase + t*8 + g)*AS + kk + qq*2;
                uint bh0 = *(const uint*)(bHi + boff);
                uint bh1 = *(const uint*)(bHi + boff + 8);
                uint bl0 = *(const uint*)(bLo + boff);
                uint bl1 = *(const uint*)(bLo + boff + 8);
                mma16816(c[t][0], c[t][1], c[t][2], c[t][3],
                         ah0, ah1, ah2, ah3, bh0, bh1);
                mma16816(c[t][0], c[t][1], c[t][2], c[t][3],
                         ah0, ah1, ah2, ah3, bl0, bl1);
                mma16816(c[t][0], c[t][1], c[t][2], c[t][3],
                         al0, al1, al2, al3, bh0, bh1);
            }
        }
    }

    // epilogue: p = sum over this warp's 104 e-cols of q*tanh(z + b_att)
    float p0 = 0.f, p1 = 0.f;
    #pragma unroll
    for (int t = 0; t < 13; ++t) {
        const int e0 = nbase + t*8 + qq*2;
        if (e0 < PE) {
            const float q0 = q_att[k*PE + e0],   bb0 = b_att[k*PE + e0];
            const float q1 = q_att[k*PE + e0+1], bb1 = b_att[k*PE + e0+1];
            p0 += q0 * tanh_fast(c[t][0] + bb0);
            p0 += q1 * tanh_fast(c[t][1] + bb1);
            p1 += q0 * tanh_fast(c[t][2] + bb0);
            p1 += q1 * tanh_fast(c[t][3] + bb1);
        }
    }
    // reduce over qq lanes
    p0 += __shfl_xor_sync(0xffffffffu, p0, 1);
    p0 += __shfl_xor_sync(0xffffffffu, p0, 2);
    p1 += __shfl_xor_sync(0xffffffffu, p1, 1);
    p1 += __shfl_xor_sync(0xffffffffu, p1, 2);
    if (qq == 0) {
        int r = r0g + mrow0 + g;
        int b = r / 100, h = r - b*100;
        atomicAdd(&s_g[(b*4 + k)*PH + h], p0);
        r += 8;
        b = r / 100; h = r - b*100;
        atomicAdd(&s_g[(b*4 + k)*PH + h], p1);
    }
}

// -----------------------------------------------------------------------------
// Kernel A2: per (b,k): softmax over s_g, u = a@his, uW = b_lin + u@W_lin[0:400]
// -----------------------------------------------------------------------------
__global__ void __launch_bounds__(256) kernelA2(
    const float* __restrict__ his,
    const float* __restrict__ W_lin, const float* __restrict__ b_lin)
{
    __shared__ float s_s[PH];
    __shared__ float u_s[PD];
    __shared__ float red_s[2];

    const int bk = blockIdx.x;
    const int b = bk >> 2, k = bk & 3;
    const int tid = threadIdx.x;
    const float* hisB = his + ((size_t)b*PH)*(PK*PD) + (size_t)k*PD;

    if (tid < PH) s_s[tid] = s_g[bk*PH + tid];
    __syncthreads();

    if (tid < 32) {
        float m = -1e30f;
        for (int h = tid; h < PH; h += 32) m = fmaxf(m, s_s[h]);
        #pragma unroll
        for (int off = 16; off; off >>= 1)
            m = fmaxf(m, __shfl_xor_sync(0xffffffffu, m, off));
        if (tid == 0) { red_s[0] = m; red_s[1] = 0.f; }
    }
    __syncthreads();
    const float mx = red_s[0];
    if (tid < PH) {
        float ex = __expf(s_s[tid] - mx);
        s_s[tid] = ex;
        atomicAdd(&red_s[1], ex);
    }
    __syncthreads();
    const float inv = 1.f / red_s[1];

    for (int d = tid; d < PD; d += 256) {
        float a0 = 0.f, a1 = 0.f;
        #pragma unroll 4
        for (int h = 0; h < PH; h += 2) {
            a0 += s_s[h]   * hisB[(size_t)h*(PK*PD) + d];
            a1 += s_s[h+1] * hisB[(size_t)(h+1)*(PK*PD) + d];
        }
        float uu = (a0 + a1) * inv;
        u_s[d] = uu;
        u_g[bk*PD + d] = uu;
    }
    __syncthreads();

    for (int e = tid; e < PE; e += 256) {
        float a0 = b_lin[e], a1 = 0.f, a2 = 0.f, a3 = 0.f;
        #pragma unroll 2
        for (int d = 0; d < PD; d += 4) {
            a0 += u_s[d]   * W_lin[(d)*PE + e];
            a1 += u_s[d+1] * W_lin[(d+1)*PE + e];
            a2 += u_s[d+2] * W_lin[(d+2)*PE + e];
            a3 += u_s[d+3] * W_lin[(d+3)*PE + e];
        }
        uW_g[bk*PE + e] = (a0 + a1) + (a2 + a3);
    }
}

// ---- Kernel C ----
__global__ void __launch_bounds__(256) kernelC(
    const float* __restrict__ cwt, const float* __restrict__ W_lin,
    const float* __restrict__ q_vec)
{
    extern __shared__ float sm[];
    float* W2 = sm;
    float* cw = W2 + PCW*PE;

    const int tid = threadIdx.x;
    const int tx = tid & 7;
    const int ty = tid >> 3;
    const int row0 = blockIdx.x * 64;

    for (int i = tid; i < PCW*PE; i += 256) W2[i] = W_lin[PD*PE + i];
    for (int i = tid; i < 64*PCW; i += 256) cw[i] = cwt[(size_t)row0*PCW + i];
    __syncthreads();

    ull acc2[2][12];
    float accS[2] = {0.f, 0.f};
    #pragma unroll
    for (int r = 0; r < 2; ++r)
        #pragma unroll
        for (int j = 0; j < 12; ++j) acc2[r][j] = 0ull;

    const float* c0p = cw + (ty*2)*PCW;
    const float* c1p = c0p + PCW;

    #pragma unroll 2
    for (int f = 0; f < PCW; ++f) {
        const float c0 = c0p[f], c1 = c1p[f];
        const ull cc0 = pack2(c0, c0), cc1 = pack2(c1, c1);
        const float* wrow = W2 + f*PE + tx*2;
        #pragma unroll
        for (int j = 0; j < 12; ++j) {
            ull w2v = *(const ull*)(wrow + j*16);
            fma2(acc2[0][j], cc0, w2v);
            fma2(acc2[1][j], cc1, w2v);
        }
        const float wl = W2[f*PE + 192 + tx];
        accS[0] += c0 * wl;
        accS[1] += c1 * wl;
    }

    #pragma unroll
    for (int rr = 0; rr < 2; ++rr) {
        const int gidx = row0 + ty*2 + rr;
        const int n = gidx >> 2, kk = gidx & 3, b = n >> 5;
        const float* uWp = uW_g + ((b << 2) + kk)*PE;
        float p = 0.f;
        #pragma unroll
        for (int j = 0; j < 12; ++j) {
            const int e = j*16 + tx*2;
            float z0, z1; unpack2(acc2[rr][j], z0, z1);
            p += q_vec[e]     * tanh_fast(z0 + uWp[e]);
            p += q_vec[e + 1] * tanh_fast(z1 + uWp[e + 1]);
        }
        {
            const int e = 192 + tx;
            p += q_vec[e] * tanh_fast(accS[rr] + uWp[e]);
        }
        p += __shfl_xor_sync(0xffffffffu, p, 1);
        p += __shfl_xor_sync(0xffffffffu, p, 2);
        p += __shfl_xor_sync(0xffffffffu, p, 4);
        if (tx == 0) sk_g[gidx] = p;
    }
}

// ---- Kernel D ----
__global__ void __launch_bounds__(128) kernelD(
    const float* __restrict__ cdd,
    float* __restrict__ out_scores, float* __restrict__ out_u)
{
    const int n = blockIdx.x;
    const int b = n >> 5;
    const int tid = threadIdx.x;
    const int k = tid >> 5;
    const int lane = tid & 31;
    __shared__ float dot_s[4];

    const float* up = u_g + (size_t)((b << 2) + k)*PD;
    const float* cp = cdd + ((size_t)n*PK + k)*PD;
    float a = 0.f;
    for (int d = lane; d < PD; d += 32) a += up[d] * cp[d];
    #pragma unroll
    for (int off = 16; off; off >>= 1)
        a += __shfl_xor_sync(0xffffffffu, a, off);
    if (lane == 0) dot_s[k] = a;
    __syncthreads();

    if (tid == 0) {
        const float s0 = sk_g[n*4], s1 = sk_g[n*4+1], s2 = sk_g[n*4+2], s3 = sk_g[n*4+3];
        const float m = fmaxf(fmaxf(s0, s1), fmaxf(s2, s3));
        const float w0 = __expf(s0 - m), w1 = __expf(s1 - m);
        const float w2 = __expf(s2 - m), w3 = __expf(s3 - m);
        out_scores[n] = (w0*dot_s[0] + w1*dot_s[1] + w2*dot_s[2] + w3*dot_s[3])
                        / (w0 + w1 + w2 + w3);
    }

    const float4* u4 = (const float4*)(u_g + (size_t)b*PK*PD);
    float4* o4 = (float4*)(out_u + (size_t)n*PK*PD);
    #pragma unroll
    for (int i = tid; i < PK*PD/4; i += 128) o4[i] = u4[i];
}

extern "C" void kernel_launch(void* const* d_in, const int* in_sizes, int n_in,
                              void* d_out, int out_size)
{
    const float* his   = (const float*)d_in[0];
    const float* cdd   = (const float*)d_in[1];
    const float* cwt   = (const float*)d_in[2];
    const float* W_att = (const float*)d_in[3];
    const float* b_att = (const float*)d_in[4];
    const float* q_att = (const float*)d_in[5];
    const float* W_lin = (const float*)d_in[6];
    const float* b_lin = (const float*)d_in[7];
    const float* q_vec = (const float*)d_in[8];
    float* out = (float*)d_out;
    (void)in_sizes; (void)n_in; (void)out_size;

    preconvHis<<<(PB*PK*PH*112 + 255)/256, 256>>>(his);
    preconvW<<<(PK*PE*112 + 255)/256, 256>>>(W_att);

    cudaFuncSetAttribute(kernelA1, cudaFuncAttributeMaxDynamicSharedMemorySize, SMEMA_BYTES);
    kernelA1<<<dim3(200, 4), 256, SMEMA_BYTES>>>(b_att, q_att);

    kernelA2<<<PB*PK, 256>>>(his, W_lin, b_lin);

    const int smemC = (PCW*PE + 64*PCW) * (int)sizeof(float);
    cudaFuncSetAttribute(kernelC, cudaFuncAttributeMaxDynamicSharedMemorySize, smemC);
    kernelC<<<(PN*PK)/64, 256, smemC>>>(cwt, W_lin, q_vec);

    kernelD<<<PN, 128>>>(cdd, out, out + PN);
}